// round 1
// baseline (speedup 1.0000x reference)
#include <cuda_runtime.h>
#include <math.h>

#define BS   128
#define GS   201
#define DIM  128
#define HALF 100
#define ROWS (BS*GS)            // 25728
#define OUTW (HALF + GS*GS)     // 40501
#define NORMC 0.08838834764831845f  // 1/sqrt(128)

// ---------------- scratch (static device globals; no allocation) ----------------
__device__ float g_gmax [BS*DIM];
__device__ float g_gproj[BS*DIM];
__device__ float g_h    [ROWS*DIM];
__device__ float g_hq   [ROWS*DIM];   // [row][head*32+c]
__device__ float g_hk   [ROWS*DIM];
__device__ float g_M    [2*4*DIM*DIM]; // M[mi][h][a][c] = sum_d Wq[h][a][d]*Wk[h][c][d]
__device__ int   g_pre  [BS*GS];
__device__ int   g_post [BS*GS];
__device__ float g_qv   [BS*16*DIM];  // [b][s(4)][head(4)][128], norm folded in
__device__ float g_U    [ROWS*32];    // [b][i][32]
__device__ float g_Vt   [BS*32*GS];   // [b][k][j] transposed for coalesced j reads

// ---------------- packed f32x2 helpers (sm_103a) ----------------
__device__ __forceinline__ unsigned long long pk2(float lo, float hi) {
    unsigned long long r;
    asm("mov.b64 %0, {%1,%2};" : "=l"(r) : "f"(lo), "f"(hi));
    return r;
}
__device__ __forceinline__ void upk2(unsigned long long v, float& lo, float& hi) {
    asm("mov.b64 {%0,%1}, %2;" : "=f"(lo), "=f"(hi) : "l"(v));
}
__device__ __forceinline__ unsigned long long ffma2(unsigned long long a, unsigned long long b, unsigned long long c) {
    unsigned long long d;
    asm("fma.rn.f32x2 %0, %1, %2, %3;" : "=l"(d) : "l"(a), "l"(b), "l"(c));
    return d;
}

// ---------------- 1: per-batch feature max + inverse/post permutations ----------------
__global__ void k_prep(const float* __restrict__ h_em, const int* __restrict__ rec) {
    int b = blockIdx.x, d = threadIdx.x;
    const float* p = h_em + (size_t)b*GS*DIM + d;
    float m = -INFINITY;
    for (int g = 0; g < GS; g++) m = fmaxf(m, p[g*DIM]);
    g_gmax[b*DIM + d] = m;
    for (int g = d; g < GS; g += DIM) {
        int r = rec[b*GS + g];
        g_pre[b*GS + r]  = g;              // inverse permutation (argsort of permutation)
        g_post[b*GS + g] = rec[b*GS + r];  // rec[rec[g]]
    }
}

// ---------------- 2: gproj = gmax @ Wg ----------------
__global__ void k_gproj(const float* __restrict__ Wg) {
    int b = blockIdx.x, d = threadIdx.x;
    __shared__ float xs[DIM];
    xs[d] = g_gmax[b*DIM + d];
    __syncthreads();
    float acc = 0.f;
    #pragma unroll 8
    for (int k = 0; k < DIM; k++) acc = fmaf(xs[k], Wg[k*DIM + d], acc);
    g_gproj[b*DIM + d] = acc;
}

// ---------------- 3: M[mi][h] = Wq[h] @ Wk[h]^T  (tiny) ----------------
__global__ void k_M(const float* __restrict__ Wq1, const float* __restrict__ Wk1,
                    const float* __restrict__ Wq2, const float* __restrict__ Wk2) {
    int blk = blockIdx.x;                 // 32 blocks
    int mi = blk >> 4, h = (blk >> 2) & 3, a0 = (blk & 3) * 32;
    const float* Wq = mi ? Wq2 : Wq1;
    const float* Wk = mi ? Wk2 : Wk1;
    __shared__ float qs[32][DIM];
    int tid = threadIdx.x;                // 128
    for (int idx = tid; idx < 32*DIM; idx += 128) {
        int a = idx >> 7, d = idx & 127;
        qs[a][d] = Wq[(h*DIM + a0 + a)*DIM + d];
    }
    __syncthreads();
    int c = tid;
    const float* wkr = Wk + (h*DIM + c)*DIM;
    for (int a = 0; a < 32; a++) {
        float acc = 0.f;
        #pragma unroll 8
        for (int d = 0; d < DIM; d++) acc = fmaf(qs[a][d], wkr[d], acc);
        g_M[((mi*4 + h)*DIM + a0 + a)*DIM + c] = acc;
    }
}

// ---------------- 4: h = h_em @ Wn + gproj (tiled fp32 GEMM) ----------------
__global__ __launch_bounds__(256) void k_h(const float* __restrict__ A, const float* __restrict__ Wn) {
    __shared__ float As[64][33];
    __shared__ float Bs[32][DIM];
    int tid = threadIdx.x;
    int ty = tid >> 4, tx = tid & 15;
    int row0 = blockIdx.x * 64;
    float acc[4][8];
    #pragma unroll
    for (int i = 0; i < 4; i++)
        #pragma unroll
        for (int j = 0; j < 8; j++) acc[i][j] = 0.f;

    for (int kt = 0; kt < DIM; kt += 32) {
        for (int idx = tid; idx < 64*32; idx += 256) {
            int r = idx >> 5, k = idx & 31;
            As[r][k] = A[(size_t)(row0 + r)*DIM + kt + k];
        }
        for (int idx = tid; idx < 32*DIM; idx += 256) {
            int k = idx >> 7, c = idx & 127;
            Bs[k][c] = Wn[(kt + k)*DIM + c];
        }
        __syncthreads();
        #pragma unroll
        for (int k = 0; k < 32; k++) {
            float a[4], bb[8];
            #pragma unroll
            for (int i = 0; i < 4; i++) a[i] = As[ty*4 + i][k];
            #pragma unroll
            for (int j = 0; j < 8; j++) bb[j] = Bs[k][tx + j*16];
            #pragma unroll
            for (int i = 0; i < 4; i++)
                #pragma unroll
                for (int j = 0; j < 8; j++) acc[i][j] = fmaf(a[i], bb[j], acc[i][j]);
        }
        __syncthreads();
    }
    #pragma unroll
    for (int i = 0; i < 4; i++) {
        int row = row0 + ty*4 + i;
        int bi = row / GS;
        #pragma unroll
        for (int j = 0; j < 8; j++) {
            int col = tx + j*16;
            g_h[(size_t)row*DIM + col] = acc[i][j] + g_gproj[bi*DIM + col];
        }
    }
}

// ---------------- 5: HQ = h @ WQr_cat, HK = h @ WKr_cat (one pass) ----------------
__global__ __launch_bounds__(256) void k_hqk(const float* __restrict__ WQr, const float* __restrict__ WKr) {
    __shared__ float As[64][33];
    __shared__ float Bq[32][DIM];
    __shared__ float Bk[32][DIM];
    int tid = threadIdx.x;
    int ty = tid >> 4, tx = tid & 15;
    int row0 = blockIdx.x * 64;
    float accq[4][8], acck[4][8];
    #pragma unroll
    for (int i = 0; i < 4; i++)
        #pragma unroll
        for (int j = 0; j < 8; j++) { accq[i][j] = 0.f; acck[i][j] = 0.f; }

    for (int kt = 0; kt < DIM; kt += 32) {
        for (int idx = tid; idx < 64*32; idx += 256) {
            int r = idx >> 5, k = idx & 31;
            As[r][k] = g_h[(size_t)(row0 + r)*DIM + kt + k];
        }
        for (int idx = tid; idx < 32*DIM; idx += 256) {
            int k = idx >> 7, n = idx & 127;
            int hh = n >> 5, c = n & 31;
            int gidx = (hh*DIM + kt + k)*32 + c;
            Bq[k][n] = WQr[gidx];
            Bk[k][n] = WKr[gidx];
        }
        __syncthreads();
        #pragma unroll
        for (int k = 0; k < 32; k++) {
            float a[4], bq[8], bk[8];
            #pragma unroll
            for (int i = 0; i < 4; i++) a[i] = As[ty*4 + i][k];
            #pragma unroll
            for (int j = 0; j < 8; j++) { bq[j] = Bq[k][tx + j*16]; bk[j] = Bk[k][tx + j*16]; }
            #pragma unroll
            for (int i = 0; i < 4; i++)
                #pragma unroll
                for (int j = 0; j < 8; j++) {
                    accq[i][j] = fmaf(a[i], bq[j], accq[i][j]);
                    acck[i][j] = fmaf(a[i], bk[j], acck[i][j]);
                }
        }
        __syncthreads();
    }
    #pragma unroll
    for (int i = 0; i < 4; i++) {
        int row = row0 + ty*4 + i;
        #pragma unroll
        for (int j = 0; j < 8; j++) {
            int col = tx + j*16;
            g_hq[(size_t)row*DIM + col] = accq[i][j];
            g_hk[(size_t)row*DIM + col] = acck[i][j];
        }
    }
}

// ---------------- 6: per-batch query vectors q = norm * x @ M[mi][h] ----------------
__global__ void k_qv(const int* __restrict__ fixed_action) {
    int sh = blockIdx.x;          // 0..15
    int b = blockIdx.y;
    int s = sh >> 2, hd = sh & 3;
    int mi = s & 1;
    int pos = 1 + fixed_action[b*3] + ((s >= 2) ? HALF : 0);
    __shared__ float xs[DIM];
    int c = threadIdx.x;
    xs[c] = g_h[((size_t)b*GS + pos)*DIM + c];
    __syncthreads();
    const float* Mp = g_M + (size_t)(mi*4 + hd)*DIM*DIM;
    float acc = 0.f;
    #pragma unroll 8
    for (int a = 0; a < DIM; a++) acc = fmaf(xs[a], Mp[a*DIM + c], acc);
    g_qv[((size_t)(b*4 + s)*4 + hd)*DIM + c] = NORMC * acc;
}

// ---------------- 7: U[b,i,:], V[b,j,:] (layer1 split of reinsertion MLP) ----------------
__global__ __launch_bounds__(256) void k_uv(const int* __restrict__ rec,
                                            const float* __restrict__ i_w1, const float* __restrict__ i_b1) {
    int b = blockIdx.y;
    int tid = threadIdx.x;
    int w = tid >> 5, l = tid & 31;
    __shared__ float w1s[16*32];
    __shared__ float b1s[32];
    for (int idx = tid; idx < 512; idx += 256) w1s[idx] = i_w1[idx];
    if (tid < 32) b1s[tid] = i_b1[tid];
    __syncthreads();
    int g = blockIdx.x * 8 + w;
    if (g >= GS) return;
    int rg = rec[b*GS + g];
    const float* hp  = g_h + ((size_t)b*GS + g )*DIM;
    const float* hnp = g_h + ((size_t)b*GS + rg)*DIM;
    float hg[4], hn[4];
    #pragma unroll
    for (int j = 0; j < 4; j++) { hg[j] = hp[l + 32*j]; hn[j] = hnp[l + 32*j]; }
    const float* qb = g_qv + (size_t)b*16*DIM;
    float cp[16];
    #pragma unroll
    for (int s = 0; s < 4; s++) {
        #pragma unroll
        for (int hd = 0; hd < 4; hd++) {
            const float* q = qb + (s*4 + hd)*DIM;
            float p = 0.f;
            #pragma unroll
            for (int j = 0; j < 4; j++) p = fmaf((s & 1) ? hn[j] : hg[j], q[l + 32*j], p);
            #pragma unroll
            for (int o = 16; o; o >>= 1) p += __shfl_xor_sync(0xffffffffu, p, o);
            cp[s*4 + hd] = p;
        }
    }
    // lane l == output channel m
    float u = 0.f, v = b1s[l];
    #pragma unroll
    for (int f = 0; f < 8; f++) {
        u = fmaf(cp[f],     w1s[f*32 + l],       u);
        v = fmaf(cp[8 + f], w1s[(8 + f)*32 + l], v);
    }
    g_U[((size_t)b*GS + g)*32 + l] = u;
    g_Vt[((size_t)b*32 + l)*GS + g] = v;
}

// ---------------- 8: big (i,j) table kernel: relu(U+V) -> 32x32 -> 32x1 -> tanh*6 ----------------
__global__ __launch_bounds__(256) void k_table(const float* __restrict__ i_w2, const float* __restrict__ i_b2,
                                               const float* __restrict__ i_w3, const float* __restrict__ i_b3,
                                               const unsigned char* __restrict__ mask,
                                               float* __restrict__ out) {
    int b = blockIdx.y;
    int i0 = blockIdx.x * 2;
    __shared__ float Vts[32*GS];
    __shared__ __align__(16) float w2s[32*32];
    __shared__ float Us[2][32];
    __shared__ float w3s[32];
    __shared__ float b2s[32];
    int tid = threadIdx.x;
    for (int idx = tid; idx < 32*GS; idx += 256) Vts[idx] = g_Vt[(size_t)b*32*GS + idx];
    for (int idx = tid; idx < 1024; idx += 256) w2s[idx] = i_w2[idx];
    if (tid < 32) { w3s[tid] = i_w3[tid]; b2s[tid] = i_b2[tid]; }
    if (tid < 64) {
        int il = tid >> 5, m = tid & 31;
        int i = i0 + il;
        Us[il][m] = (i < GS) ? g_U[((size_t)b*GS + i)*32 + m] : 0.f;
    }
    __syncthreads();

    int il = tid >> 7, jt = tid & 127;
    int i = i0 + il;
    int j1ok = (jt + 128) < GS;
    int j0 = jt, j1 = j1ok ? (jt + 128) : jt;

    unsigned long long acc0[16], acc1[16];
    #pragma unroll
    for (int m = 0; m < 16; m++) {
        unsigned long long z = pk2(b2s[2*m], b2s[2*m + 1]);
        acc0[m] = z; acc1[m] = z;
    }
    const unsigned long long* w2u = reinterpret_cast<const unsigned long long*>(w2s);
    #pragma unroll
    for (int k = 0; k < 32; k++) {
        float uk = Us[il][k];
        unsigned long long wk[16];
        #pragma unroll
        for (int m = 0; m < 16; m++) wk[m] = w2u[k*16 + m];
        float h0 = fmaxf(uk + Vts[k*GS + j0], 0.f);
        float h1 = fmaxf(uk + Vts[k*GS + j1], 0.f);
        unsigned long long hh0 = pk2(h0, h0), hh1 = pk2(h1, h1);
        #pragma unroll
        for (int m = 0; m < 16; m++) {
            acc0[m] = ffma2(hh0, wk[m], acc0[m]);
            acc1[m] = ffma2(hh1, wk[m], acc1[m]);
        }
    }
    if (i < GS) {
        float b3 = i_b3[0];
        float y0 = b3, y1 = b3;
        #pragma unroll
        for (int m = 0; m < 16; m++) {
            float a, c;
            upk2(acc0[m], a, c);
            y0 = fmaf(fmaxf(a, 0.f), w3s[2*m], y0);
            y0 = fmaf(fmaxf(c, 0.f), w3s[2*m + 1], y0);
            upk2(acc1[m], a, c);
            y1 = fmaf(fmaxf(a, 0.f), w3s[2*m], y1);
            y1 = fmaf(fmaxf(c, 0.f), w3s[2*m + 1], y1);
        }
        float t0 = tanhf(y0) * 6.f;
        float t1 = tanhf(y1) * 6.f;
        size_t mb = ((size_t)b*GS + i)*GS;
        size_t ob = (size_t)b*OUTW + HALF + (size_t)i*GS;
        if (mask[mb + j0]) t0 = -1e20f;
        out[ob + j0] = t0;
        if (j1ok) {
            if (mask[mb + j1]) t1 = -1e20f;
            out[ob + j1] = t1;
        }
    }
}

// ---------------- 9: removal table ----------------
__global__ void k_removal(const float* __restrict__ sel,
                          const float* __restrict__ rw1, const float* __restrict__ rb1,
                          const float* __restrict__ rw2, const float* __restrict__ rb2,
                          const float* __restrict__ rw3, const float* __restrict__ rb3,
                          float* __restrict__ out) {
    int b = blockIdx.x, i = threadIdx.x;   // 128 threads
    __shared__ float w1s[12*32], b1s[32], w2s[32*32], b2s[32], w3s[32];
    for (int idx = i; idx < 12*32; idx += 128) w1s[idx] = rw1[idx];
    for (int idx = i; idx < 32*32; idx += 128) w2s[idx] = rw2[idx];
    if (i < 32) { b1s[i] = rb1[i]; b2s[i] = rb2[i]; w3s[i] = rw3[i]; }
    __syncthreads();
    if (i >= HALF) return;
    float feat[12];
    #pragma unroll
    for (int k8 = 0; k8 < 8; k8++) {
        int hd = k8 & 3;
        int g = (k8 < 4) ? (1 + i) : (1 + HALF + i);
        int gp = g_pre[b*GS + g], gq = g_post[b*GS + g];
        const float* qp = g_hq + ((size_t)b*GS + gp)*DIM + hd*32;
        const float* qg = g_hq + ((size_t)b*GS + g )*DIM + hd*32;
        const float* kg = g_hk + ((size_t)b*GS + g )*DIM + hd*32;
        const float* kq = g_hk + ((size_t)b*GS + gq)*DIM + hd*32;
        float s = 0.f;
        #pragma unroll
        for (int c = 0; c < 32; c++) s += qp[c]*kg[c] + qg[c]*kq[c] - qp[c]*kq[c];
        feat[k8] = s;
    }
    #pragma unroll
    for (int c = 0; c < 4; c++) feat[8 + c] = sel[((size_t)b*4 + c)*HALF + i];
    float x1[32];
    #pragma unroll
    for (int m = 0; m < 32; m++) {
        float a = b1s[m];
        #pragma unroll
        for (int f = 0; f < 12; f++) a = fmaf(feat[f], w1s[f*32 + m], a);
        x1[m] = fmaxf(a, 0.f);
    }
    float y = rb3[0];
    #pragma unroll
    for (int m = 0; m < 32; m++) {
        float a = b2s[m];
        #pragma unroll
        for (int k = 0; k < 32; k++) a = fmaf(x1[k], w2s[k*32 + m], a);
        y = fmaf(fmaxf(a, 0.f), w3s[m], y);
    }
    out[(size_t)b*OUTW + i] = tanhf(y) * 6.f;
}

// ---------------- 10: in-place softmax over out[b, off : off+n] ----------------
__global__ void k_softmax(float* __restrict__ out, int off, int n) {
    int b = blockIdx.x, tid = threadIdx.x;
    float* p = out + (size_t)b*OUTW + off;
    __shared__ float red[256];
    __shared__ float sv[2];
    float m = -INFINITY;
    for (int idx = tid; idx < n; idx += 256) m = fmaxf(m, p[idx]);
    red[tid] = m; __syncthreads();
    for (int o = 128; o; o >>= 1) { if (tid < o) red[tid] = fmaxf(red[tid], red[tid + o]); __syncthreads(); }
    if (tid == 0) sv[0] = red[0];
    __syncthreads();
    float mx = sv[0];
    float s = 0.f;
    for (int idx = tid; idx < n; idx += 256) s += expf(p[idx] - mx);
    red[tid] = s; __syncthreads();
    for (int o = 128; o; o >>= 1) { if (tid < o) red[tid] += red[tid + o]; __syncthreads(); }
    if (tid == 0) sv[1] = 1.f / red[0];
    __syncthreads();
    float inv = sv[1];
    for (int idx = tid; idx < n; idx += 256) p[idx] = expf(p[idx] - mx) * inv;
}

// ---------------- launch ----------------
extern "C" void kernel_launch(void* const* d_in, const int* in_sizes, int n_in,
                              void* d_out, int out_size) {
    const float* h_em = (const float*)d_in[0];
    const float* sel  = (const float*)d_in[1];
    const float* Wn   = (const float*)d_in[2];
    const float* Wg   = (const float*)d_in[3];
    const float* WQr  = (const float*)d_in[4];
    const float* WKr  = (const float*)d_in[5];
    const float* rw1  = (const float*)d_in[6];
    const float* rb1  = (const float*)d_in[7];
    const float* rw2  = (const float*)d_in[8];
    const float* rb2  = (const float*)d_in[9];
    const float* rw3  = (const float*)d_in[10];
    const float* rb3  = (const float*)d_in[11];
    const float* Wq1  = (const float*)d_in[12];
    const float* Wk1  = (const float*)d_in[13];
    const float* Wq2  = (const float*)d_in[14];
    const float* Wk2  = (const float*)d_in[15];
    const float* iw1  = (const float*)d_in[16];
    const float* ib1  = (const float*)d_in[17];
    const float* iw2  = (const float*)d_in[18];
    const float* ib2  = (const float*)d_in[19];
    const float* iw3  = (const float*)d_in[20];
    const float* ib3  = (const float*)d_in[21];
    const int*   rec  = (const int*)d_in[22];
    const int*   fa   = (const int*)d_in[23];
    const unsigned char* mask = (const unsigned char*)d_in[24];
    float* out = (float*)d_out;

    k_prep   <<<BS, DIM>>>(h_em, rec);
    k_gproj  <<<BS, DIM>>>(Wg);
    k_M      <<<32, 128>>>(Wq1, Wk1, Wq2, Wk2);
    k_h      <<<ROWS/64, 256>>>(h_em, Wn);
    k_hqk    <<<ROWS/64, 256>>>(WQr, WKr);
    k_qv     <<<dim3(16, BS), 128>>>(fa);
    k_uv     <<<dim3(26, BS), 256>>>(rec, iw1, ib1);
    k_table  <<<dim3(101, BS), 256>>>(iw2, ib2, iw3, ib3, mask, out);
    k_removal<<<BS, 128>>>(sel, rw1, rb1, rw2, rb2, rw3, rb3, out);
    k_softmax<<<BS, 256>>>(out, 0, HALF);
    k_softmax<<<BS, 256>>>(out, HALF, GS*GS);
}

// round 8
// speedup vs baseline: 1.2928x; 1.2928x over previous
#include <cuda_runtime.h>
#include <math.h>
#include <stdint.h>

#define BS   128
#define GS   201
#define DIM  128
#define HALF 100
#define ROWS (BS*GS)            // 25728
#define OUTW (HALF + GS*GS)     // 40501
#define NPOS (GS*GS)            // 40401
#define NORMC 0.08838834764831845f  // 1/sqrt(128)

#define T_PER_B 316             // ceil(40401/128)
#define CHUNKS  3
#define TILES_PER_CHUNK 106

// ---------------- scratch (static device globals; no allocation) ----------------
__device__ float g_gproj[BS*DIM];
__device__ float g_h    [ROWS*DIM];
__device__ float g_hq   [ROWS*DIM];
__device__ float g_hk   [ROWS*DIM];
__device__ int   g_pre  [BS*GS];
__device__ int   g_post [BS*GS];
__device__ float g_qv   [BS*16*DIM];  // [b][s(4)][head(4)][128], norm folded in
__device__ float g_U    [ROWS*32];    // [b][i][32]
__device__ float g_V    [ROWS*32];    // [b][j][32]

// ---------------- helpers ----------------
__device__ __forceinline__ uint32_t tf32u(float x) {
    uint32_t r; asm("cvt.rna.tf32.f32 %0, %1;" : "=r"(r) : "f"(x)); return r;
}
// m16n8k8 tf32 MMA (portable PTX, HMMA path on sm_103)
__device__ __forceinline__ void mma8(float* c, const uint32_t* a, const uint32_t* b) {
    asm volatile(
        "mma.sync.aligned.m16n8k8.row.col.f32.tf32.tf32.f32 "
        "{%0,%1,%2,%3}, {%4,%5,%6,%7}, {%8,%9}, {%0,%1,%2,%3};"
        : "+f"(c[0]), "+f"(c[1]), "+f"(c[2]), "+f"(c[3])
        : "r"(a[0]), "r"(a[1]), "r"(a[2]), "r"(a[3]), "r"(b[0]), "r"(b[1]));
}

// ---------------- 1: per-batch max -> gproj + permutations (merged) ----------------
__global__ void k_prep(const float* __restrict__ h_em, const int* __restrict__ rec,
                       const float* __restrict__ Wg) {
    int b = blockIdx.x, d = threadIdx.x;
    __shared__ float xs[DIM];
    const float* p = h_em + (size_t)b*GS*DIM + d;
    float m = -INFINITY;
    for (int g = 0; g < GS; g++) m = fmaxf(m, p[g*DIM]);
    xs[d] = m;
    for (int g = d; g < GS; g += DIM) {
        int r = rec[b*GS + g];
        g_pre[b*GS + r]  = g;
        g_post[b*GS + g] = rec[b*GS + r];
    }
    __syncthreads();
    float acc = 0.f;
    #pragma unroll 8
    for (int k = 0; k < DIM; k++) acc = fmaf(xs[k], Wg[k*DIM + d], acc);
    g_gproj[b*DIM + d] = acc;
}

// ---------------- 2: h = h_em @ Wn + gproj ----------------
__global__ __launch_bounds__(256) void k_h(const float* __restrict__ A, const float* __restrict__ Wn) {
    __shared__ float As[64][33];
    __shared__ float Bs[32][DIM];
    int tid = threadIdx.x;
    int ty = tid >> 4, tx = tid & 15;
    int row0 = blockIdx.x * 64;
    float acc[4][8];
    #pragma unroll
    for (int i = 0; i < 4; i++)
        #pragma unroll
        for (int j = 0; j < 8; j++) acc[i][j] = 0.f;

    for (int kt = 0; kt < DIM; kt += 32) {
        for (int idx = tid; idx < 64*32; idx += 256) {
            int r = idx >> 5, k = idx & 31;
            As[r][k] = A[(size_t)(row0 + r)*DIM + kt + k];
        }
        for (int idx = tid; idx < 32*DIM; idx += 256) {
            int k = idx >> 7, c = idx & 127;
            Bs[k][c] = Wn[(kt + k)*DIM + c];
        }
        __syncthreads();
        #pragma unroll
        for (int k = 0; k < 32; k++) {
            float a[4], bb[8];
            #pragma unroll
            for (int i = 0; i < 4; i++) a[i] = As[ty*4 + i][k];
            #pragma unroll
            for (int j = 0; j < 8; j++) bb[j] = Bs[k][tx + j*16];
            #pragma unroll
            for (int i = 0; i < 4; i++)
                #pragma unroll
                for (int j = 0; j < 8; j++) acc[i][j] = fmaf(a[i], bb[j], acc[i][j]);
        }
        __syncthreads();
    }
    #pragma unroll
    for (int i = 0; i < 4; i++) {
        int row = row0 + ty*4 + i;
        int bi = row / GS;
        #pragma unroll
        for (int j = 0; j < 8; j++) {
            int col = tx + j*16;
            g_h[(size_t)row*DIM + col] = acc[i][j] + g_gproj[bi*DIM + col];
        }
    }
}

// ---------------- 3: query vectors q[h] = norm * Wk[h]^T (Wq[h]^T x)  (kd = DIM) ----------------
__global__ void k_qv(const int* __restrict__ fixed_action,
                     const float* __restrict__ Wq1, const float* __restrict__ Wk1,
                     const float* __restrict__ Wq2, const float* __restrict__ Wk2) {
    int sh = blockIdx.x;          // 0..15
    int b = blockIdx.y;
    int s = sh >> 2, hd = sh & 3;
    const float* Wq = (s & 1) ? Wq2 : Wq1;
    const float* Wk = (s & 1) ? Wk2 : Wk1;
    int pos = 1 + fixed_action[b*3] + ((s >= 2) ? HALF : 0);
    __shared__ float xs[DIM];
    __shared__ float ts[DIM];
    int c = threadIdx.x;          // 128
    xs[c] = g_h[((size_t)b*GS + pos)*DIM + c];
    __syncthreads();
    float t = 0.f;
    #pragma unroll 8
    for (int i = 0; i < DIM; i++) t = fmaf(xs[i], Wq[(hd*DIM + i)*DIM + c], t);
    ts[c] = t;
    __syncthreads();
    const float* wkr = Wk + (hd*DIM + c)*DIM;
    float acc = 0.f;
    #pragma unroll 8
    for (int k = 0; k < DIM; k++) acc = fmaf(ts[k], wkr[k], acc);
    g_qv[((size_t)(b*4 + s)*4 + hd)*DIM + c] = NORMC * acc;
}

// ---------------- 4: U[b,i,:], V[b,j,:] ----------------
__global__ __launch_bounds__(256) void k_uv(const int* __restrict__ rec,
                                            const float* __restrict__ i_w1, const float* __restrict__ i_b1) {
    int b = blockIdx.y;
    int tid = threadIdx.x;
    int w = tid >> 5, l = tid & 31;
    __shared__ float w1s[16*32];
    __shared__ float b1s[32];
    for (int idx = tid; idx < 512; idx += 256) w1s[idx] = i_w1[idx];
    if (tid < 32) b1s[tid] = i_b1[tid];
    __syncthreads();
    int g = blockIdx.x * 8 + w;
    if (g >= GS) return;
    int rg = rec[b*GS + g];
    const float* hp  = g_h + ((size_t)b*GS + g )*DIM;
    const float* hnp = g_h + ((size_t)b*GS + rg)*DIM;
    float hg[4], hn[4];
    #pragma unroll
    for (int j = 0; j < 4; j++) { hg[j] = hp[l + 32*j]; hn[j] = hnp[l + 32*j]; }
    const float* qb = g_qv + (size_t)b*16*DIM;
    float cp[16];
    #pragma unroll
    for (int s = 0; s < 4; s++) {
        #pragma unroll
        for (int hd = 0; hd < 4; hd++) {
            const float* q = qb + (s*4 + hd)*DIM;
            float p = 0.f;
            #pragma unroll
            for (int j = 0; j < 4; j++) p = fmaf((s & 1) ? hn[j] : hg[j], q[l + 32*j], p);
            #pragma unroll
            for (int o = 16; o; o >>= 1) p += __shfl_xor_sync(0xffffffffu, p, o);
            cp[s*4 + hd] = p;
        }
    }
    float u = 0.f, v = b1s[l];
    #pragma unroll
    for (int f = 0; f < 8; f++) {
        u = fmaf(cp[f],     w1s[f*32 + l],       u);
        v = fmaf(cp[8 + f], w1s[(8 + f)*32 + l], v);
    }
    g_U[((size_t)b*GS + g)*32 + l] = u;
    g_V[((size_t)b*GS + g)*32 + l] = v;
}

// ---------------- 5: HQ/HK projections (kd=32 heads) ----------------
__global__ __launch_bounds__(256) void k_hqk(const float* __restrict__ WQr, const float* __restrict__ WKr) {
    __shared__ float As[64][33];
    __shared__ float Bq[32][DIM];
    __shared__ float Bk[32][DIM];
    int tid = threadIdx.x;
    int ty = tid >> 4, tx = tid & 15;
    int row0 = blockIdx.x * 64;
    float accq[4][8], acck[4][8];
    #pragma unroll
    for (int i = 0; i < 4; i++)
        #pragma unroll
        for (int j = 0; j < 8; j++) { accq[i][j] = 0.f; acck[i][j] = 0.f; }

    for (int kt = 0; kt < DIM; kt += 32) {
        for (int idx = tid; idx < 64*32; idx += 256) {
            int r = idx >> 5, k = idx & 31;
            As[r][k] = g_h[(size_t)(row0 + r)*DIM + kt + k];
        }
        for (int idx = tid; idx < 32*DIM; idx += 256) {
            int k = idx >> 7, n = idx & 127;
            int hh = n >> 5, c = n & 31;
            int gidx = (hh*DIM + kt + k)*32 + c;
            Bq[k][n] = WQr[gidx];
            Bk[k][n] = WKr[gidx];
        }
        __syncthreads();
        #pragma unroll
        for (int k = 0; k < 32; k++) {
            float a[4], bq[8], bk[8];
            #pragma unroll
            for (int i = 0; i < 4; i++) a[i] = As[ty*4 + i][k];
            #pragma unroll
            for (int j = 0; j < 8; j++) { bq[j] = Bq[k][tx + j*16]; bk[j] = Bk[k][tx + j*16]; }
            #pragma unroll
            for (int i = 0; i < 4; i++)
                #pragma unroll
                for (int j = 0; j < 8; j++) {
                    accq[i][j] = fmaf(a[i], bq[j], accq[i][j]);
                    acck[i][j] = fmaf(a[i], bk[j], acck[i][j]);
                }
        }
        __syncthreads();
    }
    #pragma unroll
    for (int i = 0; i < 4; i++) {
        int row = row0 + ty*4 + i;
        #pragma unroll
        for (int j = 0; j < 8; j++) {
            int col = tx + j*16;
            g_hq[(size_t)row*DIM + col] = accq[i][j];
            g_hk[(size_t)row*DIM + col] = acck[i][j];
        }
    }
}

// ---------------- 6: big (i,j) table via warp-level tf32 mma.sync (3-term split) ----------------
// smem (floats): U [201*34], V [201*34], b2[32], w3[32], b3[1]
#define USTR 34
#define SM_U 0
#define SM_V (GS*USTR)
#define SM_B2 (2*GS*USTR)
#define SM_W3 (SM_B2 + 32)
#define SM_B3 (SM_W3 + 32)
#define SMEM_TABLE ((SM_B3 + 8) * 4)

__global__ __launch_bounds__(256) void k_table(const float* __restrict__ i_w2, const float* __restrict__ i_b2,
                                               const float* __restrict__ i_w3, const float* __restrict__ i_b3,
                                               const unsigned char* __restrict__ mask,
                                               float* __restrict__ out) {
    extern __shared__ float sm[];
    float* Us  = sm + SM_U;
    float* Vs  = sm + SM_V;
    float* b2s = sm + SM_B2;
    float* w3s = sm + SM_W3;
    float* b3s = sm + SM_B3;
    const int tid = threadIdx.x;
    const int w = tid >> 5, lane = tid & 31;
    const int gid = lane >> 2, tig = lane & 3;
    const int b = blockIdx.y;
    const int chunk = blockIdx.x;

    // stage U/V (padded stride 34: Us broadcasts, Vs <=2-way conflicts)
    for (int idx = tid; idx < GS*32; idx += 256) {
        int r = idx >> 5, c = idx & 31;
        Us[r*USTR + c] = g_U[(size_t)b*GS*32 + idx];
        Vs[r*USTR + c] = g_V[(size_t)b*GS*32 + idx];
    }
    if (tid < 32) { b2s[tid] = i_b2[tid]; w3s[tid] = i_w3[tid]; }
    if (tid == 0) b3s[0] = i_b3[0];

    // B fragments: w2[k][m], col-major 8x8 blocks; loop-invariant, resident in regs
    uint32_t bh[4][4][2], bl[4][4][2];
    #pragma unroll
    for (int kb = 0; kb < 4; kb++) {
        #pragma unroll
        for (int nb = 0; nb < 4; nb++) {
            float w0 = i_w2[(kb*8 + tig    )*32 + nb*8 + gid];
            float w1 = i_w2[(kb*8 + tig + 4)*32 + nb*8 + gid];
            uint32_t h0 = tf32u(w0), h1 = tf32u(w1);
            bh[kb][nb][0] = h0; bh[kb][nb][1] = h1;
            bl[kb][nb][0] = tf32u(w0 - __uint_as_float(h0));
            bl[kb][nb][1] = tf32u(w1 - __uint_as_float(h1));
        }
    }
    __syncthreads();

    int t0 = chunk * TILES_PER_CHUNK;
    int t1 = min(t0 + TILES_PER_CHUNK, T_PER_B);

    for (int t = t0; t < t1; t++) {
        int gp0 = t*128 + w*16 + gid;          // row p0 (this thread's quad)
        int gq0 = min(gp0, NPOS - 1);
        int gq1 = min(gp0 + 8, NPOS - 1);
        int i0 = gq0 / GS, j0 = gq0 - i0*GS;
        int i1 = gq1 / GS, j1 = gq1 - i1*GS;
        const float* u0 = Us + i0*USTR;
        const float* v0 = Vs + j0*USTR;
        const float* u1 = Us + i1*USTR;
        const float* v1 = Vs + j1*USTR;

        float C[4][4];
        #pragma unroll
        for (int nb = 0; nb < 4; nb++)
            #pragma unroll
            for (int q = 0; q < 4; q++) C[nb][q] = 0.f;

        #pragma unroll
        for (int kb = 0; kb < 4; kb++) {
            int k0 = kb*8 + tig, k1 = k0 + 4;
            float a0 = fmaxf(u0[k0] + v0[k0], 0.f);   // (p0, k0)
            float a1 = fmaxf(u1[k0] + v1[k0], 0.f);   // (p1, k0)
            float a2 = fmaxf(u0[k1] + v0[k1], 0.f);   // (p0, k1)
            float a3 = fmaxf(u1[k1] + v1[k1], 0.f);   // (p1, k1)
            uint32_t ah[4], al[4];
            ah[0] = tf32u(a0); al[0] = tf32u(a0 - __uint_as_float(ah[0]));
            ah[1] = tf32u(a1); al[1] = tf32u(a1 - __uint_as_float(ah[1]));
            ah[2] = tf32u(a2); al[2] = tf32u(a2 - __uint_as_float(ah[2]));
            ah[3] = tf32u(a3); al[3] = tf32u(a3 - __uint_as_float(ah[3]));
            #pragma unroll
            for (int nb = 0; nb < 4; nb++) {
                mma8(C[nb], ah, bh[kb][nb]);
                mma8(C[nb], al, bh[kb][nb]);
                mma8(C[nb], ah, bl[kb][nb]);
            }
        }

        // layer-3 epilogue in registers
        float y0 = 0.f, y1 = 0.f;
        #pragma unroll
        for (int nb = 0; nb < 4; nb++) {
            int m = nb*8 + 2*tig;
            float b2a = b2s[m], b2b = b2s[m + 1];
            float w3a = w3s[m], w3b = w3s[m + 1];
            y0 += fmaxf(C[nb][0] + b2a, 0.f)*w3a + fmaxf(C[nb][1] + b2b, 0.f)*w3b;
            y1 += fmaxf(C[nb][2] + b2a, 0.f)*w3a + fmaxf(C[nb][3] + b2b, 0.f)*w3b;
        }
        y0 += __shfl_xor_sync(0xffffffffu, y0, 1);
        y0 += __shfl_xor_sync(0xffffffffu, y0, 2);
        y1 += __shfl_xor_sync(0xffffffffu, y1, 1);
        y1 += __shfl_xor_sync(0xffffffffu, y1, 2);

        if (tig == 0) {
            float b3 = b3s[0];
            if (gp0 < NPOS) {
                float vv = tanhf(y0 + b3) * 6.f;
                if (mask[(size_t)b*NPOS + gp0]) vv = -1e20f;
                out[(size_t)b*OUTW + HALF + gp0] = vv;
            }
            int gpB = gp0 + 8;
            if (gpB < NPOS) {
                float vv = tanhf(y1 + b3) * 6.f;
                if (mask[(size_t)b*NPOS + gpB]) vv = -1e20f;
                out[(size_t)b*OUTW + HALF + gpB] = vv;
            }
        }
    }
}

// ---------------- 7: removal table ----------------
__global__ void k_removal(const float* __restrict__ sel,
                          const float* __restrict__ rw1, const float* __restrict__ rb1,
                          const float* __restrict__ rw2, const float* __restrict__ rb2,
                          const float* __restrict__ rw3, const float* __restrict__ rb3,
                          float* __restrict__ out) {
    int b = blockIdx.x, i = threadIdx.x;
    __shared__ float w1s[12*32], b1s[32], w2s[32*32], b2s[32], w3s[32];
    for (int idx = i; idx < 12*32; idx += 128) w1s[idx] = rw1[idx];
    for (int idx = i; idx < 32*32; idx += 128) w2s[idx] = rw2[idx];
    if (i < 32) { b1s[i] = rb1[i]; b2s[i] = rb2[i]; w3s[i] = rw3[i]; }
    __syncthreads();
    if (i >= HALF) return;
    float feat[12];
    #pragma unroll
    for (int k8 = 0; k8 < 8; k8++) {
        int hd = k8 & 3;
        int g = (k8 < 4) ? (1 + i) : (1 + HALF + i);
        int gp = g_pre[b*GS + g], gq = g_post[b*GS + g];
        const float* qp = g_hq + ((size_t)b*GS + gp)*DIM + hd*32;
        const float* qg = g_hq + ((size_t)b*GS + g )*DIM + hd*32;
        const float* kg = g_hk + ((size_t)b*GS + g )*DIM + hd*32;
        const float* kq = g_hk + ((size_t)b*GS + gq)*DIM + hd*32;
        float s = 0.f;
        #pragma unroll
        for (int c = 0; c < 32; c++) s += qp[c]*kg[c] + qg[c]*kq[c] - qp[c]*kq[c];
        feat[k8] = s;
    }
    #pragma unroll
    for (int c = 0; c < 4; c++) feat[8 + c] = sel[((size_t)b*4 + c)*HALF + i];
    float x1[32];
    #pragma unroll
    for (int m = 0; m < 32; m++) {
        float a = b1s[m];
        #pragma unroll
        for (int f = 0; f < 12; f++) a = fmaf(feat[f], w1s[f*32 + m], a);
        x1[m] = fmaxf(a, 0.f);
    }
    float y = rb3[0];
    #pragma unroll
    for (int m = 0; m < 32; m++) {
        float a = b2s[m];
        #pragma unroll
        for (int k = 0; k < 32; k++) a = fmaf(x1[k], w2s[k*32 + m], a);
        y = fmaf(fmaxf(a, 0.f), w3s[m], y);
    }
    out[(size_t)b*OUTW + i] = tanhf(y) * 6.f;
}

// ---------------- 8: in-place softmax over out[b, off : off+n] ----------------
template <int NT>
__global__ void k_softmax(float* __restrict__ out, int off, int n) {
    int b = blockIdx.x, tid = threadIdx.x;
    float* p = out + (size_t)b*OUTW + off;
    __shared__ float red[NT];
    __shared__ float sv[2];
    float m = -INFINITY;
    for (int idx = tid; idx < n; idx += NT) m = fmaxf(m, p[idx]);
    red[tid] = m; __syncthreads();
    for (int o = NT/2; o; o >>= 1) { if (tid < o) red[tid] = fmaxf(red[tid], red[tid + o]); __syncthreads(); }
    if (tid == 0) sv[0] = red[0];
    __syncthreads();
    float mx = sv[0];
    float s = 0.f;
    for (int idx = tid; idx < n; idx += NT) s += expf(p[idx] - mx);
    red[tid] = s; __syncthreads();
    for (int o = NT/2; o; o >>= 1) { if (tid < o) red[tid] += red[tid + o]; __syncthreads(); }
    if (tid == 0) sv[1] = 1.f / red[0];
    __syncthreads();
    float inv = sv[1];
    for (int idx = tid; idx < n; idx += NT) p[idx] = expf(p[idx] - mx) * inv;
}

// ---------------- launch ----------------
extern "C" void kernel_launch(void* const* d_in, const int* in_sizes, int n_in,
                              void* d_out, int out_size) {
    const float* h_em = (const float*)d_in[0];
    const float* sel  = (const float*)d_in[1];
    const float* Wn   = (const float*)d_in[2];
    const float* Wg   = (const float*)d_in[3];
    const float* WQr  = (const float*)d_in[4];
    const float* WKr  = (const float*)d_in[5];
    const float* rw1  = (const float*)d_in[6];
    const float* rb1  = (const float*)d_in[7];
    const float* rw2  = (const float*)d_in[8];
    const float* rb2  = (const float*)d_in[9];
    const float* rw3  = (const float*)d_in[10];
    const float* rb3  = (const float*)d_in[11];
    const float* Wq1  = (const float*)d_in[12];
    const float* Wk1  = (const float*)d_in[13];
    const float* Wq2  = (const float*)d_in[14];
    const float* Wk2  = (const float*)d_in[15];
    const float* iw1  = (const float*)d_in[16];
    const float* ib1  = (const float*)d_in[17];
    const float* iw2  = (const float*)d_in[18];
    const float* ib2  = (const float*)d_in[19];
    const float* iw3  = (const float*)d_in[20];
    const float* ib3  = (const float*)d_in[21];
    const int*   rec  = (const int*)d_in[22];
    const int*   fa   = (const int*)d_in[23];
    const unsigned char* mask = (const unsigned char*)d_in[24];
    float* out = (float*)d_out;

    cudaFuncSetAttribute(k_table, cudaFuncAttributeMaxDynamicSharedMemorySize, SMEM_TABLE);

    k_prep   <<<BS, DIM>>>(h_em, rec, Wg);
    k_h      <<<ROWS/64, 256>>>(h_em, Wn);
    k_qv     <<<dim3(16, BS), 128>>>(fa, Wq1, Wk1, Wq2, Wk2);
    k_uv     <<<dim3(26, BS), 256>>>(rec, iw1, ib1);
    k_hqk    <<<ROWS/64, 256>>>(WQr, WKr);
    k_table  <<<dim3(CHUNKS, BS), 256, SMEM_TABLE>>>(iw2, ib2, iw3, ib3, mask, out);
    k_removal<<<BS, 128>>>(sel, rw1, rb1, rw2, rb2, rw3, rb3, out);
    k_softmax<128><<<BS, 128>>>(out, 0, HALF);
    k_softmax<1024><<<BS, 1024>>>(out, HALF, GS*GS);
}